// round 3
// baseline (speedup 1.0000x reference)
#include <cuda_runtime.h>
#include <cstdint>

#define BB 16
#define QL 32
#define TN 10
#define AL 10
#define EE 300
#define EP 301
#define HH 256
#define NEGV -10000000000.0f

// ---- shared memory layout (floats) ----
#define OFF_W     0              // sim_w split: w1,w2,w3 (900)
#define OFF_QE    900            // q_emb [QL][EP] = 9632
#define OFF_ENCT  10532          // encT [600][12] = 7200   (byte off 42128, 16B aligned)
#define OFF_ATT   17732          // atten [AL][QL] = 320
#define OFF_ATTS  18052          // softmaxed      = 320
#define OFF_QW2   18372          // 32
#define OFF_QM    18404          // 32
#define OFF_AW1   18436          // 16
#define OFF_AM    18452          // 16
#define OFF_PART  18468          // partial [3][128][10] = 3840
#define OFF_RED   22308          // 8
#define SMEM_FLOATS 22316
#define SMEM_BYTES (SMEM_FLOATS * 4)

__device__ float g_max_atten[BB * TN * QL];
__device__ float g_score_half[2][BB * TN];

__device__ __forceinline__ void fma_f32x2(unsigned long long& acc,
                                          unsigned long long a,
                                          unsigned long long b)
{
    asm("fma.rn.f32x2 %0, %1, %2, %0;" : "+l"(acc) : "l"(a), "l"(b));
}

__global__ void __launch_bounds__(512, 2)
topic_kernelA(const int* __restrict__ q, const int* __restrict__ alia,
              const float* __restrict__ emb, const float* __restrict__ sim_w,
              const float* __restrict__ sim_b, const float* __restrict__ enc_w,
              const float* __restrict__ enc_b, const float* __restrict__ qlin_w)
{
    extern __shared__ float sm[];
    float* w1      = sm + OFF_W;
    float* w2      = w1 + EE;
    float* w3      = w2 + EE;
    float* q_emb   = sm + OFF_QE;
    float* encT    = sm + OFF_ENCT;
    float* atten   = sm + OFF_ATT;
    float* attensm = sm + OFF_ATTS;
    float* qW2     = sm + OFF_QW2;
    float* qmaskS  = sm + OFF_QM;
    float* aW1     = sm + OFF_AW1;
    float* amaskS  = sm + OFF_AM;
    float* partial = sm + OFF_PART;
    float* red     = sm + OFF_RED;

    const int tid  = threadIdx.x;
    const int lane = tid & 31;
    const int wid  = tid >> 5;              // 0..15
    const int job  = blockIdx.x >> 1;       // 0..159  (b*TN + t)
    const int half = blockIdx.x & 1;        // h-half: 0 -> h 0..127, 1 -> 128..255
    const int b    = job / TN;
    const int t    = job - b * TN;

    const float simb = sim_b[0];

    // ---- sim_w -> smem ----
    for (int i = tid; i < 3 * EE; i += 512) sm[OFF_W + i] = sim_w[i];
    __syncthreads();

    // ---- gather + normalize q rows (warp per row) + qW2 dot ----
    for (int j = wid; j < QL; j += 16) {
        int idx = q[b * QL + j];
        float x[10];
        float ss = 0.f;
        #pragma unroll
        for (int i = 0; i < 10; i++) {
            int e = lane + 32 * i;
            float v = (e < EE) ? emb[(size_t)idx * EE + e] : 0.f;
            x[i] = v;
            ss += v * v;
        }
        #pragma unroll
        for (int o = 16; o; o >>= 1) ss += __shfl_xor_sync(0xffffffffu, ss, o);
        float scale = (idx == 0) ? 0.f : 1.f / fmaxf(sqrtf(ss), 1e-12f);
        float dot = 0.f;
        #pragma unroll
        for (int i = 0; i < 10; i++) {
            int e = lane + 32 * i;
            if (e < EE) {
                float v = x[i] * scale;
                q_emb[j * EP + e] = v;
                dot += v * w2[e];
            }
        }
        #pragma unroll
        for (int o = 16; o; o >>= 1) dot += __shfl_xor_sync(0xffffffffu, dot, o);
        if (lane == 0) {
            qW2[j]    = dot;
            qmaskS[j] = (idx != 0) ? 1.f : 0.f;
        }
    }

    // ---- gather + normalize alias rows (warps 0..9) -> encT[300..599], aW1 dot ----
    if (wid < AL) {
        int a = wid;
        int idx = alia[(b * TN + t) * AL + a];
        float x[10];
        float ss = 0.f;
        #pragma unroll
        for (int i = 0; i < 10; i++) {
            int e = lane + 32 * i;
            float v = (e < EE) ? emb[(size_t)idx * EE + e] : 0.f;
            x[i] = v;
            ss += v * v;
        }
        #pragma unroll
        for (int o = 16; o; o >>= 1) ss += __shfl_xor_sync(0xffffffffu, ss, o);
        float scale = (idx == 0) ? 0.f : 1.f / fmaxf(sqrtf(ss), 1e-12f);
        float dot = 0.f;
        #pragma unroll
        for (int i = 0; i < 10; i++) {
            int e = lane + 32 * i;
            if (e < EE) {
                float v = x[i] * scale;
                encT[(300 + e) * 12 + a] = v;    // second half of enc_in, transposed
                dot += v * w1[e];
            }
        }
        #pragma unroll
        for (int o = 16; o; o >>= 1) dot += __shfl_xor_sync(0xffffffffu, dot, o);
        if (lane == 0) {
            aW1[a]    = dot;
            amaskS[a] = (idx != 0) ? 1.f : 0.f;
        }
    }
    __syncthreads();

    // ---- attention scores: warp = a, lane = q (alias row read from encT, broadcast) ----
    if (wid < AL) {
        int a = wid, qi = lane;
        const float* qe = q_emb + qi * EP;
        float d = 0.f;
        for (int e = 0; e < EE; e++) d += encT[(300 + e) * 12 + a] * w3[e] * qe[e];
        float val = aW1[a] + qW2[qi] + d + simb;
        float m = amaskS[a] * qmaskS[qi];
        atten[a * QL + qi] = m * val + (1.f - m) * NEGV;
    }
    __syncthreads();

    // ---- softmax over q per alias row; max over a (warp 10, half 0 only writes) ----
    if (wid < AL) {
        int a = wid;
        float v = atten[a * QL + lane];
        float mx = v;
        #pragma unroll
        for (int o = 16; o; o >>= 1) mx = fmaxf(mx, __shfl_xor_sync(0xffffffffu, mx, o));
        float ex = expf(v - mx);
        float s = ex;
        #pragma unroll
        for (int o = 16; o; o >>= 1) s += __shfl_xor_sync(0xffffffffu, s, o);
        attensm[a * QL + lane] = ex / s;
    }
    if (wid == 10 && half == 0) {
        float mx = atten[lane];
        #pragma unroll
        for (int a = 1; a < AL; a++) mx = fmaxf(mx, atten[a * QL + lane]);
        g_max_atten[(b * TN + t) * QL + lane] = mx;
    }
    __syncthreads();

    // ---- alig[a][e] = sum_q attensm[a][q] * q_emb[q][e] -> encT rows 0..299 ----
    for (int p = tid; p < AL * EE; p += 512) {
        int a = p / EE, e = p - a * EE;
        const float* as = attensm + a * QL;
        float s = 0.f;
        #pragma unroll
        for (int qi = 0; qi < QL; qi++) s += as[qi] * q_emb[qi * EP + e];
        encT[e * 12 + a] = s;
    }
    __syncthreads();

    // ---- enc GEMM (this block's 128-wide h-half), packed f32x2 FMA ----
    {
        const int h   = tid & 127;         // 0..127 within half
        const int qtr = tid >> 7;          // e-quarter 0..3 (150 e each)
        const int hh  = half * 128 + h;    // global h

        unsigned long long acc01 = 0ull, acc23 = 0ull, acc45 = 0ull,
                           acc67 = 0ull, acc89 = 0ull;

        const float* W = enc_w + hh;
        const int e0 = qtr * 150;
        #pragma unroll 2
        for (int e = e0; e < e0 + 150; e++) {
            float w = W[(size_t)e * HH];
            unsigned long long wp;
            uint32_t wu = __float_as_uint(w);
            asm("mov.b64 %0, {%1, %1};" : "=l"(wp) : "r"(wu));

            const ulonglong2* r = reinterpret_cast<const ulonglong2*>(encT + e * 12);
            ulonglong2 p0 = r[0];          // a0a1, a2a3
            ulonglong2 p1 = r[1];          // a4a5, a6a7
            unsigned long long p2 =
                *reinterpret_cast<const unsigned long long*>(encT + e * 12 + 8);

            fma_f32x2(acc01, p0.x, wp);
            fma_f32x2(acc23, p0.y, wp);
            fma_f32x2(acc45, p1.x, wp);
            fma_f32x2(acc67, p1.y, wp);
            fma_f32x2(acc89, p2, wp);
        }

        float acc[10];
        acc[0] = __uint_as_float((uint32_t)acc01); acc[1] = __uint_as_float((uint32_t)(acc01 >> 32));
        acc[2] = __uint_as_float((uint32_t)acc23); acc[3] = __uint_as_float((uint32_t)(acc23 >> 32));
        acc[4] = __uint_as_float((uint32_t)acc45); acc[5] = __uint_as_float((uint32_t)(acc45 >> 32));
        acc[6] = __uint_as_float((uint32_t)acc67); acc[7] = __uint_as_float((uint32_t)(acc67 >> 32));
        acc[8] = __uint_as_float((uint32_t)acc89); acc[9] = __uint_as_float((uint32_t)(acc89 >> 32));

        __syncthreads();
        if (qtr != 0) {
            float* dst = partial + (qtr - 1) * 1280 + h * 10;
            #pragma unroll
            for (int a = 0; a < AL; a++) dst[a] = acc[a];
        }
        __syncthreads();

        float val = 0.f;
        if (qtr == 0) {                     // warps 0..3 entirely
            float eb = enc_b[hh];
            float qw = qlin_w[hh];
            float s = 0.f;
            #pragma unroll
            for (int a = 0; a < AL; a++) {
                float encv = acc[a] + partial[h * 10 + a] + partial[1280 + h * 10 + a]
                           + partial[2560 + h * 10 + a] + eb;
                s += fmaxf(encv, 0.f);
            }
            val = s * qw;
            #pragma unroll
            for (int o = 16; o; o >>= 1) val += __shfl_xor_sync(0xffffffffu, val, o);
            if (lane == 0) red[wid] = val;
        }
        __syncthreads();
        if (tid == 0) {
            float s = red[0] + red[1] + red[2] + red[3];
            g_score_half[half][job] = s;
        }
    }
}

__global__ void topic_kernelB(const float* __restrict__ els, const float* __restrict__ elo,
                              const float* __restrict__ cate, const float* __restrict__ cls_w,
                              const float* __restrict__ cls_b, const float* __restrict__ qlin_b,
                              float* __restrict__ out)
{
    int b = threadIdx.x >> 5;     // warp per batch, 16 warps
    int lane = threadIdx.x & 31;

    float c0w = cls_w[0], c1w = cls_w[1], c2w = cls_w[2], c3w = cls_w[3], c4w = cls_w[4];
    float cb = cls_b[0];
    float qb = qlin_b[0];

    float ml[TN];
    #pragma unroll
    for (int t = 0; t < TN; t++) {
        float eo = elo[b * TN + t];
        float es = els[b * TN + t];
        float ca = cate[(b * TN + t) * 2 + 0];
        float cbv = cate[(b * TN + t) * 2 + 1];
        float as = g_score_half[0][b * TN + t] + g_score_half[1][b * TN + t] + qb;
        float lg = eo * c0w + es * c1w + ca * c2w + cbv * c3w + as * c4w + cb;
        float tm = ((es + eo) != 0.f) ? 1.f : 0.f;
        ml[t] = tm * lg + (1.f - tm) * NEGV;
    }
    if (lane < TN) out[b * TN + lane] = ml[lane];

    // softmax over topics (redundant per lane, cheap)
    float mx = ml[0];
    #pragma unroll
    for (int t = 1; t < TN; t++) mx = fmaxf(mx, ml[t]);
    float p[TN];
    float sum = 0.f;
    #pragma unroll
    for (int t = 0; t < TN; t++) { p[t] = expf(ml[t] - mx); sum += p[t]; }
    float inv = 1.f / sum;

    // weighted max-attention, softmax over q (lane = q)
    float s = 0.f;
    #pragma unroll
    for (int t = 0; t < TN; t++)
        s += p[t] * inv * g_max_atten[(b * TN + t) * QL + lane];

    float m2 = s;
    #pragma unroll
    for (int o = 16; o; o >>= 1) m2 = fmaxf(m2, __shfl_xor_sync(0xffffffffu, m2, o));
    float ex = expf(s - m2);
    float tot = ex;
    #pragma unroll
    for (int o = 16; o; o >>= 1) tot += __shfl_xor_sync(0xffffffffu, tot, o);
    out[BB * TN + b * QL + lane] = ex / tot;
}

extern "C" void kernel_launch(void* const* d_in, const int* in_sizes, int n_in,
                              void* d_out, int out_size)
{
    const int*   q      = (const int*)  d_in[0];
    const int*   alia   = (const int*)  d_in[1];
    const float* els    = (const float*)d_in[2];
    const float* elo    = (const float*)d_in[3];
    const float* cate   = (const float*)d_in[4];
    const float* emb    = (const float*)d_in[5];
    const float* sim_w  = (const float*)d_in[6];
    const float* sim_b  = (const float*)d_in[7];
    const float* enc_w  = (const float*)d_in[8];
    const float* enc_b  = (const float*)d_in[9];
    const float* qlin_w = (const float*)d_in[10];
    const float* qlin_b = (const float*)d_in[11];
    const float* cls_w  = (const float*)d_in[12];
    const float* cls_b  = (const float*)d_in[13];
    float* out = (float*)d_out;

    cudaFuncSetAttribute(topic_kernelA, cudaFuncAttributeMaxDynamicSharedMemorySize, SMEM_BYTES);

    topic_kernelA<<<BB * TN * 2, 512, SMEM_BYTES>>>(q, alia, emb, sim_w, sim_b,
                                                    enc_w, enc_b, qlin_w);
    topic_kernelB<<<1, 512>>>(els, elo, cate, cls_w, cls_b, qlin_b, out);
}